// round 16
// baseline (speedup 1.0000x reference)
#include <cuda_runtime.h>
#include <math.h>
#include <cstdint>

#define B_  64
#define T_  2048
#define I_  128
#define H_  256

#define NG 16      // batch groups
#define NS 8       // hidden slices per group
#define NB 4       // batches per group = 2 chains x 2 batches
#define NU 32      // hidden units per slice
#define THREADS 256

#define WXSTRIDE 132   // %32==4 -> conflict-free LDS.128 weight rows
#define WNSTRIDE 260   // %32==4, rows 16B-aligned

// ---- SMEM layout (float offsets) ----
#define OFF_WX   0                          // [g3][u32][k128] rows stride 132 = 12672
#define OFF_WN   12672                      // gate-n W_hh: [u32][k256] stride 260 = 8320
#define OFF_BR   20992
#define OFF_BZ   21024
#define OFF_BIN  21056
#define OFF_BHN  21088
#define OFF_X    21120                      // [lane2][par2][b2][128] = 1024
#define OFF_H    22144                      // [lane2][b2][256] = 1024
#define OFF_PX   23168                      // [lane2][par2][(g3*b2)][ch2][u32] = 1536
#define OFF_PH   24704                      // [lane2][par2][(g3*b2)][ch4][u32] = 3072
#define SMEM_FLOATS 27776
#define SMEM_BYTES  (SMEM_FLOATS * 4)       // ~111 KB

typedef unsigned long long ull;

// Self-validating h exchange: [grp][parity][b][unit] of packed {tag:32 | h:32}.
// tag = t+1 means "h_t". Cleared by out kernel each launch (graph-replay safe).
#define EXCH_WORDS (NG * 2 * NB * 256)      // 32768 u64
__device__ ull g_exch[EXCH_WORDS];

__device__ __forceinline__ uint32_t smem_u32(const void* p) {
    uint32_t a;
    asm("{ .reg .u64 t; cvta.to.shared.u64 t, %1; cvt.u32.u64 %0, t; }" : "=r"(a) : "l"(p));
    return a;
}
#define FFMA2(d, a, b) \
    asm volatile("fma.rn.f32x2 %0, %1, %2, %0;" : "+l"(d) : "l"(a), "l"(b))

__device__ __forceinline__ float psum(ull v) {
    unsigned lo, hi;
    asm("mov.b64 {%0,%1}, %2;" : "=r"(lo), "=r"(hi) : "l"(v));
    return __uint_as_float(lo) + __uint_as_float(hi);
}
__device__ __forceinline__ ull packf2(float a, float b) {
    ull w;
    asm("mov.b64 %0, {%1,%2};" : "=l"(w) : "r"(__float_as_uint(a)), "r"(__float_as_uint(b)));
    return w;
}
__device__ __forceinline__ void st_relaxed_u64(ull* p, ull v) {
    asm volatile("st.relaxed.gpu.global.u64 [%0], %1;" :: "l"(p), "l"(v) : "memory");
}
__device__ __forceinline__ void ld_relaxed_v2u64(const ull* p, ull& a, ull& b) {
    asm volatile("ld.relaxed.gpu.global.v2.u64 {%0,%1}, [%2];"
                 : "=l"(a), "=l"(b) : "l"(p) : "memory");
}
#define BAR_SYNC128(id) asm volatile("bar.sync %0, 128;" :: "r"(id) : "memory")

__global__ void __launch_bounds__(THREADS, 1)
gru_scan_kernel(const float* __restrict__ x,
                const float* __restrict__ Wih,
                const float* __restrict__ Whh,
                const float* __restrict__ bih,
                const float* __restrict__ bhh,
                float* __restrict__ outbuf)
{
    extern __shared__ float smem[];
    const int tid = threadIdx.x;
    const int cta = blockIdx.x;
    const int grp = cta >> 3;
    const int slc = cta & 7;
    const int b0  = grp * NB;
    const int u0  = slc * NU;
    const uint32_t sbase = smem_u32(smem);

    float* hid = outbuf + (size_t)B_ * T_;   // hiddens [B][T][H]

    const int wid  = tid >> 5;
    const int u    = tid & 31;
    const int lane = wid >> 2;               // chain 0 (batches 0-1) or 1 (batches 2-3)
    const int w_in = wid & 3;                // warp within lane
    const int bb0  = lane * 2;               // chain's first batch (within group)
    const int kw   = w_in * 64;              // this warp's h K-chunk
    // role split balanced across SMSPs: lane A x-warps = w_in even; lane B = w_in odd
    const bool is_x = ((w_in & 1) == lane);
    const int  role_b = w_in >> 1;           // x-warp: K chunk idx; combine warp: batch-in-chain
    const int  barid  = 1 + lane;

    // ---- one-time: W_ih (3 gates) into SMEM ----
    for (int rk = tid; rk < 96 * 128; rk += THREADS) {
        int row = rk >> 7, k = rk & 127;
        int g = row >> 5, uu = row & 31;
        smem[OFF_WX + (g * 32 + uu) * WXSTRIDE + k] =
            Wih[(size_t)(g * 256 + u0 + uu) * I_ + k];
    }
    // ---- one-time: W_hh gate n into SMEM [u][k256] ----
    for (int rk = tid; rk < 32 * 256; rk += THREADS) {
        int row = rk >> 8, k = rk & 255;
        smem[OFF_WN + row * WNSTRIDE + k] =
            Whh[(size_t)(2 * 256 + u0 + row) * H_ + k];
    }
    if (tid < 32) {
        int uu = tid;
        smem[OFF_BR  + uu] = bih[0 * 256 + u0 + uu] + bhh[0 * 256 + u0 + uu];
        smem[OFF_BZ  + uu] = bih[1 * 256 + u0 + uu] + bhh[1 * 256 + u0 + uu];
        smem[OFF_BIN + uu] = bih[2 * 256 + u0 + uu];
        smem[OFF_BHN + uu] = bhh[2 * 256 + u0 + uu];
    }
    // preload x_0 for both chains into parity-0 slots
    for (int e = tid; e < 512; e += THREADS) {
        int ln = e >> 8, rem = e & 255;
        int bl = rem >> 7, k = rem & 127;
        smem[OFF_X + ln * 512 + bl * 128 + k] =
            x[((size_t)(b0 + ln * 2 + bl) * T_ + 0) * I_ + k];
    }

    // ---- one-time: W_hh gates r,z (this warp's K-chunk of 64) into REGISTERS ----
    ull wh[64];
    #pragma unroll
    for (int g = 0; g < 2; ++g) {
        const float* row = Whh + (size_t)(g * 256 + u0 + u) * H_ + kw;
        #pragma unroll
        for (int j = 0; j < 32; ++j) {
            float2 v = *reinterpret_cast<const float2*>(row + 2 * j);
            wh[g * 32 + j] = packf2(v.x, v.y);
        }
    }
    __syncthreads();

    const float* wnrow = smem + OFF_WN + u * WNSTRIDE;          // gate-n W_hh row
    float* hb = smem + OFF_H + lane * 512;                      // chain h staging
    const float rBR  = smem[OFF_BR + u];
    const float rBZ  = smem[OFF_BZ + u];
    const float rBIN = smem[OFF_BIN + u];
    const float rBHN = smem[OFF_BHN + u];

    float hprev_reg = 0.f;                                      // combine warps only
    const int pbx = u >> 4;                                     // prefetch: batch-in-chain
    const int pox = (u & 15) * 4;                               //           16B slice

    // ---- prologue (x-warps): px(0) into parity 0; prefetch x(1) into parity 1 ----
    if (is_x) {
        const int kx = role_b * 64;
        const float* wx0 = smem + OFF_WX + (0 * 32 + u) * WXSTRIDE;
        const float* wx1 = smem + OFF_WX + (1 * 32 + u) * WXSTRIDE;
        const float* wx2 = smem + OFF_WX + (2 * 32 + u) * WXSTRIDE;
        ull acc[6];
        #pragma unroll
        for (int i = 0; i < 6; ++i) acc[i] = 0ull;
        const float* xq = smem + OFF_X + lane * 512;            // parity 0
        #pragma unroll
        for (int j = 0; j < 16; ++j) {
            const int k = kx + 4 * j;
            ulonglong2 x0 = *reinterpret_cast<const ulonglong2*>(xq + 0 * 128 + k);
            ulonglong2 x1 = *reinterpret_cast<const ulonglong2*>(xq + 1 * 128 + k);
            ulonglong2 w0 = *reinterpret_cast<const ulonglong2*>(wx0 + k);
            ulonglong2 w1 = *reinterpret_cast<const ulonglong2*>(wx1 + k);
            ulonglong2 w2 = *reinterpret_cast<const ulonglong2*>(wx2 + k);
            FFMA2(acc[0], w0.x, x0.x); FFMA2(acc[0], w0.y, x0.y);
            FFMA2(acc[1], w0.x, x1.x); FFMA2(acc[1], w0.y, x1.y);
            FFMA2(acc[2], w1.x, x0.x); FFMA2(acc[2], w1.y, x0.y);
            FFMA2(acc[3], w1.x, x1.x); FFMA2(acc[3], w1.y, x1.y);
            FFMA2(acc[4], w2.x, x0.x); FFMA2(acc[4], w2.y, x0.y);
            FFMA2(acc[5], w2.x, x1.x); FFMA2(acc[5], w2.y, x1.y);
        }
        float* px = smem + OFF_PX + lane * 768;                 // parity 0
        #pragma unroll
        for (int g = 0; g < 3; ++g)
            #pragma unroll
            for (int bl = 0; bl < 2; ++bl)
                px[((g * 2 + bl) * 2 + role_b) * 32 + u] = psum(acc[g * 2 + bl]);
        // prefetch x(1) -> parity 1 (self-sufficient: this warp's own K-chunk, both batches)
        {
            uint32_t dst = sbase + (OFF_X + lane * 512 + 256 + pbx * 128 + kx + pox) * 4;
            const float* src = x + ((size_t)(b0 + bb0 + pbx) * T_ + 1) * I_ + kx + pox;
            asm volatile("cp.async.cg.shared.global [%0], [%1], 16;" :: "r"(dst), "l"(src));
            asm volatile("cp.async.commit_group;" ::: "memory");
        }
    }

    for (int t = 0; t < T_; ++t) {
        const int p = t & 1;
        const int q = p ^ 1;

        if (t > 0) {
            // ---- poll own K-chunk (2 batches, v2 loads), stage hb, h-GEMM ----
            const ull* ep = g_exch + (size_t)(grp * 2 + ((t - 1) & 1)) * 1024;
            const ull* e0 = ep + (bb0 + 0) * 256 + kw + 2 * u;
            const ull* e1 = ep + (bb0 + 1) * 256 + kw + 2 * u;
            const unsigned tgt = (unsigned)t;
            ull a0, a1, c0, c1;
            for (;;) {
                ld_relaxed_v2u64(e0, a0, a1);
                ld_relaxed_v2u64(e1, c0, c1);
                bool ok = (unsigned)(a0 >> 32) == tgt && (unsigned)(a1 >> 32) == tgt &&
                          (unsigned)(c0 >> 32) == tgt && (unsigned)(c1 >> 32) == tgt;
                if (__all_sync(0xffffffffu, ok)) break;
            }
            *reinterpret_cast<float2*>(hb + 0 * 256 + kw + 2 * u) =
                make_float2(__uint_as_float((unsigned)a0), __uint_as_float((unsigned)a1));
            *reinterpret_cast<float2*>(hb + 1 * 256 + kw + 2 * u) =
                make_float2(__uint_as_float((unsigned)c0), __uint_as_float((unsigned)c1));
            __syncwarp();

            ull acc[6];
            #pragma unroll
            for (int i = 0; i < 6; ++i) acc[i] = 0ull;
            #pragma unroll
            for (int jj = 0; jj < 16; ++jj) {
                const int k = kw + 4 * jj;
                ulonglong2 h0 = *reinterpret_cast<const ulonglong2*>(hb + 0 * 256 + k);
                ulonglong2 h1 = *reinterpret_cast<const ulonglong2*>(hb + 1 * 256 + k);
                // gates r,z from registers
                #pragma unroll
                for (int g = 0; g < 2; ++g) {
                    const ull wa = wh[g * 32 + 2 * jj];
                    const ull wb = wh[g * 32 + 2 * jj + 1];
                    FFMA2(acc[g * 2 + 0], wa, h0.x); FFMA2(acc[g * 2 + 0], wb, h0.y);
                    FFMA2(acc[g * 2 + 1], wa, h1.x); FFMA2(acc[g * 2 + 1], wb, h1.y);
                }
                // gate n from SMEM row
                ulonglong2 wn = *reinterpret_cast<const ulonglong2*>(wnrow + k);
                FFMA2(acc[4], wn.x, h0.x); FFMA2(acc[4], wn.y, h0.y);
                FFMA2(acc[5], wn.x, h1.x); FFMA2(acc[5], wn.y, h1.y);
            }
            float* ph = smem + OFF_PH + lane * 1536 + p * 768;
            #pragma unroll
            for (int g = 0; g < 3; ++g)
                #pragma unroll
                for (int bl = 0; bl < 2; ++bl)
                    ph[((g * 2 + bl) * 4 + w_in) * 32 + u] = psum(acc[g * 2 + bl]);
        }

        BAR_SYNC128(barid);   // lane rendezvous: ph(t) + px(t) visible; buffer reuse ordered

        if (is_x) {
            // ---- x pipeline for step t+1 (off the chain's critical path) ----
            if (t + 1 < T_) {
                const int kx = role_b * 64;
                asm volatile("cp.async.wait_group 0;" ::: "memory");   // x(t+1) resident
                if (t + 2 < T_) {
                    uint32_t dst = sbase + (OFF_X + lane * 512 + p * 256 + pbx * 128 + kx + pox) * 4;
                    const float* src = x + ((size_t)(b0 + bb0 + pbx) * T_ + (t + 2)) * I_ + kx + pox;
                    asm volatile("cp.async.cg.shared.global [%0], [%1], 16;" :: "r"(dst), "l"(src));
                    asm volatile("cp.async.commit_group;" ::: "memory");
                }
                const float* wx0 = smem + OFF_WX + (0 * 32 + u) * WXSTRIDE;
                const float* wx1 = smem + OFF_WX + (1 * 32 + u) * WXSTRIDE;
                const float* wx2 = smem + OFF_WX + (2 * 32 + u) * WXSTRIDE;
                ull acc[6];
                #pragma unroll
                for (int i = 0; i < 6; ++i) acc[i] = 0ull;
                const float* xq = smem + OFF_X + lane * 512 + q * 256;
                #pragma unroll
                for (int j = 0; j < 16; ++j) {
                    const int k = kx + 4 * j;
                    ulonglong2 x0 = *reinterpret_cast<const ulonglong2*>(xq + 0 * 128 + k);
                    ulonglong2 x1 = *reinterpret_cast<const ulonglong2*>(xq + 1 * 128 + k);
                    ulonglong2 w0 = *reinterpret_cast<const ulonglong2*>(wx0 + k);
                    ulonglong2 w1 = *reinterpret_cast<const ulonglong2*>(wx1 + k);
                    ulonglong2 w2 = *reinterpret_cast<const ulonglong2*>(wx2 + k);
                    FFMA2(acc[0], w0.x, x0.x); FFMA2(acc[0], w0.y, x0.y);
                    FFMA2(acc[1], w0.x, x1.x); FFMA2(acc[1], w0.y, x1.y);
                    FFMA2(acc[2], w1.x, x0.x); FFMA2(acc[2], w1.y, x0.y);
                    FFMA2(acc[3], w1.x, x1.x); FFMA2(acc[3], w1.y, x1.y);
                    FFMA2(acc[4], w2.x, x0.x); FFMA2(acc[4], w2.y, x0.y);
                    FFMA2(acc[5], w2.x, x1.x); FFMA2(acc[5], w2.y, x1.y);
                }
                float* px = smem + OFF_PX + lane * 768 + q * 384;
                #pragma unroll
                for (int g = 0; g < 3; ++g)
                    #pragma unroll
                    for (int bl = 0; bl < 2; ++bl)
                        px[((g * 2 + bl) * 2 + role_b) * 32 + u] = psum(acc[g * 2 + bl]);
            }
        } else {
            // ---- combine + publish (batch = bb0 + role_b, unit = u0+u) ----
            const int bl = role_b;
            const float* px = smem + OFF_PX + lane * 768 + p * 384;
            float sx0, sx1, sx2;
            sx0 = px[((0 * 2 + bl) * 2 + 0) * 32 + u] + px[((0 * 2 + bl) * 2 + 1) * 32 + u];
            sx1 = px[((1 * 2 + bl) * 2 + 0) * 32 + u] + px[((1 * 2 + bl) * 2 + 1) * 32 + u];
            sx2 = px[((2 * 2 + bl) * 2 + 0) * 32 + u] + px[((2 * 2 + bl) * 2 + 1) * 32 + u];
            float sh0 = 0.f, sh1 = 0.f, sh2 = 0.f;
            if (t > 0) {
                const float* ph = smem + OFF_PH + lane * 1536 + p * 768;
                #pragma unroll
                for (int c = 0; c < 4; ++c) {
                    sh0 += ph[((0 * 2 + bl) * 4 + c) * 32 + u];
                    sh1 += ph[((1 * 2 + bl) * 4 + c) * 32 + u];
                    sh2 += ph[((2 * 2 + bl) * 4 + c) * 32 + u];
                }
            }
            const float pre_r = sx0 + sh0 + rBR;
            const float pre_z = sx1 + sh1 + rBZ;
            const float r = __fdividef(1.f, 1.f + __expf(-pre_r));
            const float z = __fdividef(1.f, 1.f + __expf(-pre_z));
            const float v = (sx2 + rBIN) + r * (sh2 + rBHN);
            const float nn = 1.f - __fdividef(2.f, __expf(2.f * v) + 1.f);   // tanh(v)
            const float hnew = (1.f - z) * nn + z * hprev_reg;
            hprev_reg = hnew;

            const int bg = bb0 + bl;   // batch within group
            const ull pk = ((ull)(unsigned)(t + 1) << 32) | (ull)__float_as_uint(hnew);
            st_relaxed_u64(g_exch + (size_t)(grp * 2 + p) * 1024 + bg * 256 + u0 + u, pk);

            hid[((size_t)(b0 + bg) * T_ + t) * H_ + u0 + u] = hnew;
        }
    }
}

// outputs[b,t] = hiddens[b,t,:] . W_o + b_o ; clears exchange tags for graph replay
__global__ void gru_out_kernel(const float* __restrict__ Wo,
                               const float* __restrict__ bo,
                               float* __restrict__ outbuf)
{
    if (blockIdx.x < 128)
        g_exch[(size_t)blockIdx.x * 256 + threadIdx.x] = 0ull;

    int gw   = (int)((blockIdx.x * blockDim.x + threadIdx.x) >> 5);
    int lane = threadIdx.x & 31;
    if (gw >= B_ * T_) return;

    const float* hrow = outbuf + (size_t)B_ * T_ + (size_t)gw * H_;
    float s = 0.f;
    #pragma unroll
    for (int c = 0; c < 8; ++c) {
        int k = c * 32 + lane;
        s += hrow[k] * __ldg(&Wo[k]);
    }
    #pragma unroll
    for (int off = 16; off; off >>= 1)
        s += __shfl_xor_sync(0xffffffffu, s, off);
    if (lane == 0) outbuf[gw] = s + __ldg(&bo[0]);
}

extern "C" void kernel_launch(void* const* d_in, const int* in_sizes, int n_in,
                              void* d_out, int out_size)
{
    const float* x   = (const float*)d_in[0];
    const float* Wih = (const float*)d_in[1];
    const float* Whh = (const float*)d_in[2];
    const float* bih = (const float*)d_in[3];
    const float* bhh = (const float*)d_in[4];
    const float* Wo  = (const float*)d_in[5];
    const float* bo  = (const float*)d_in[6];
    float* out = (float*)d_out;

    cudaFuncSetAttribute(gru_scan_kernel,
                         cudaFuncAttributeMaxDynamicSharedMemorySize, SMEM_BYTES);

    gru_scan_kernel<<<NG * NS, THREADS, SMEM_BYTES>>>(x, Wih, Whh, bih, bhh, out);
    gru_out_kernel<<<(B_ * T_ * 32) / 256, 256>>>(Wo, bo, out);
}